// round 1
// baseline (speedup 1.0000x reference)
#include <cuda_runtime.h>
#include <math.h>

#define BATCH 16384
#define HDIM  1024
#define NJ    64

// Scratch activations (allocation-free contract: __device__ globals)
__device__ float g_h1[BATCH * HDIM];
__device__ float g_h2[BATCH * HDIM];
__device__ float g_joints[BATCH * 256];

// ---------------------------------------------------------------------------
// Layer 1: h1 = leaky_relu(x @ W1 + b1),  x:[B,3], W1:[3,1024]
// ---------------------------------------------------------------------------
__global__ void layer1_kernel(const float* __restrict__ x,
                              const float* __restrict__ W1,
                              const float* __restrict__ b1,
                              float* __restrict__ out) {
    int idx = blockIdx.x * blockDim.x + threadIdx.x;   // over BATCH*HDIM
    int b = idx >> 10;
    int n = idx & (HDIM - 1);
    float x0 = x[b * 3 + 0];
    float x1 = x[b * 3 + 1];
    float x2 = x[b * 3 + 2];
    float v = b1[n];
    v = fmaf(x2, W1[2 * HDIM + n], v);
    v = fmaf(x1, W1[1 * HDIM + n], v);
    v = fmaf(x0, W1[0 * HDIM + n], v);
    out[idx] = (v >= 0.0f) ? v : 0.01f * v;
}

// ---------------------------------------------------------------------------
// SIMT fp32 GEMM: C[M,N] = act(A[M,K] @ B[K,N] + bias)
// Block tile 128x128, K-tile 8, 256 threads, 8x8 per-thread tile.
// ACT: 0 = leaky_relu, 1 = tanh
// Requires M%128==0, N%128==0, K%8==0 (true for all layers here).
// ---------------------------------------------------------------------------
template <int ACT>
__global__ __launch_bounds__(256, 2)
void gemm_bias_act(const float* __restrict__ A,
                   const float* __restrict__ Bm,
                   const float* __restrict__ bias,
                   float* __restrict__ C,
                   int M, int N, int K) {
    __shared__ float As[8][128];
    __shared__ float Bs[8][128];

    const int tid = threadIdx.x;
    const int tx  = tid & 15;        // 0..15 -> N direction
    const int ty  = tid >> 4;        // 0..15 -> M direction
    const int m0  = blockIdx.y * 128;
    const int n0  = blockIdx.x * 128;

    // A-tile load mapping: 128 rows x 8 k, float4 along K
    const int a_m = tid >> 1;              // 0..127
    const int a_k = (tid & 1) * 4;         // 0 or 4
    // B-tile load mapping: 8 k-rows x 128 n, float4 along N
    const int b_k = tid >> 5;              // 0..7
    const int b_n = (tid & 31) * 4;        // 0..124

    const float* Aptr = A + (size_t)(m0 + a_m) * K + a_k;
    const float* Bptr = Bm + (size_t)b_k * N + n0 + b_n;

    float acc[8][8];
#pragma unroll
    for (int i = 0; i < 8; i++)
#pragma unroll
        for (int j = 0; j < 8; j++) acc[i][j] = 0.0f;

    for (int k0 = 0; k0 < K; k0 += 8) {
        float4 av = *reinterpret_cast<const float4*>(Aptr);
        As[a_k + 0][a_m] = av.x;
        As[a_k + 1][a_m] = av.y;
        As[a_k + 2][a_m] = av.z;
        As[a_k + 3][a_m] = av.w;
        *reinterpret_cast<float4*>(&Bs[b_k][b_n]) =
            *reinterpret_cast<const float4*>(Bptr);
        __syncthreads();

#pragma unroll
        for (int kk = 0; kk < 8; kk++) {
            float af[8], bf[8];
            *reinterpret_cast<float4*>(af)     = *reinterpret_cast<float4*>(&As[kk][ty * 8]);
            *reinterpret_cast<float4*>(af + 4) = *reinterpret_cast<float4*>(&As[kk][ty * 8 + 4]);
            *reinterpret_cast<float4*>(bf)     = *reinterpret_cast<float4*>(&Bs[kk][tx * 8]);
            *reinterpret_cast<float4*>(bf + 4) = *reinterpret_cast<float4*>(&Bs[kk][tx * 8 + 4]);
#pragma unroll
            for (int i = 0; i < 8; i++)
#pragma unroll
                for (int j = 0; j < 8; j++)
                    acc[i][j] = fmaf(af[i], bf[j], acc[i][j]);
        }
        __syncthreads();

        Aptr += 8;
        Bptr += (size_t)8 * N;
    }

    // Epilogue: bias + activation, float4 stores
    float bvals[8];
#pragma unroll
    for (int j = 0; j < 8; j++) bvals[j] = bias[n0 + tx * 8 + j];

#pragma unroll
    for (int i = 0; i < 8; i++) {
        int row = m0 + ty * 8 + i;
        float* crow = C + (size_t)row * N + n0 + tx * 8;
        float vals[8];
#pragma unroll
        for (int j = 0; j < 8; j++) {
            float v = acc[i][j] + bvals[j];
            if (ACT == 0) {
                vals[j] = (v >= 0.0f) ? v : 0.01f * v;
            } else {
                vals[j] = tanhf(v);
            }
        }
        *reinterpret_cast<float4*>(crow)     = *reinterpret_cast<const float4*>(vals);
        *reinterpret_cast<float4*>(crow + 4) = *reinterpret_cast<const float4*>(vals + 4);
    }
}

// ---------------------------------------------------------------------------
// FK chain: per batch element, 64 sequential joints.
// Homogeneous 4x4 chain reduces exactly to:
//   R = quat_to_mat3(q);  rot_new = rot_prev @ R;  t_new = t_prev + rot_new[:,1]
// (T translates by (0,1,0); bottom rows stay exactly [0,0,0,1] so w == 1.0f
//  and w + 1e-9f == 1.0f in fp32 -> output is just t.)
// ---------------------------------------------------------------------------
__global__ void fk_kernel(const float* __restrict__ joints,
                          float* __restrict__ out) {
    int b = blockIdx.x * blockDim.x + threadIdx.x;
    if (b >= BATCH) return;

    const float4* q4 = reinterpret_cast<const float4*>(joints + (size_t)b * 256);
    float* o = out + (size_t)b * NJ * 3;

    float r00 = 1.f, r01 = 0.f, r02 = 0.f;
    float r10 = 0.f, r11 = 1.f, r12 = 0.f;
    float r20 = 0.f, r21 = 0.f, r22 = 1.f;
    float t0 = 0.f, t1 = 0.f, t2 = 0.f;

    for (int j = 0; j < NJ; j++) {
        float4 q = q4[j];
        float w = q.x, x = q.y, y = q.z, z = q.w;
        float s = 2.0f / (w * w + x * x + y * y + z * z);

        float R00 = 1.0f - s * (y * y + z * z);
        float R01 = s * (x * y - z * w);
        float R02 = s * (x * z + y * w);
        float R10 = s * (x * y + z * w);
        float R11 = 1.0f - s * (x * x + z * z);
        float R12 = s * (y * z - x * w);
        float R20 = s * (x * z - y * w);
        float R21 = s * (y * z + x * w);
        float R22 = 1.0f - s * (x * x + y * y);

        float n00 = r00 * R00 + r01 * R10 + r02 * R20;
        float n01 = r00 * R01 + r01 * R11 + r02 * R21;
        float n02 = r00 * R02 + r01 * R12 + r02 * R22;
        float n10 = r10 * R00 + r11 * R10 + r12 * R20;
        float n11 = r10 * R01 + r11 * R11 + r12 * R21;
        float n12 = r10 * R02 + r11 * R12 + r12 * R22;
        float n20 = r20 * R00 + r21 * R10 + r22 * R20;
        float n21 = r20 * R01 + r21 * R11 + r22 * R21;
        float n22 = r20 * R02 + r21 * R12 + r22 * R22;

        t0 += n01;
        t1 += n11;
        t2 += n21;

        r00 = n00; r01 = n01; r02 = n02;
        r10 = n10; r11 = n11; r12 = n12;
        r20 = n20; r21 = n21; r22 = n22;

        o[j * 3 + 0] = t0;
        o[j * 3 + 1] = t1;
        o[j * 3 + 2] = t2;
    }
}

// ---------------------------------------------------------------------------
// Launch
// ---------------------------------------------------------------------------
extern "C" void kernel_launch(void* const* d_in, const int* in_sizes, int n_in,
                              void* d_out, int out_size) {
    const float* x  = (const float*)d_in[0];
    const float* W1 = (const float*)d_in[1];
    const float* b1 = (const float*)d_in[2];
    const float* W2 = (const float*)d_in[3];
    const float* b2 = (const float*)d_in[4];
    const float* W3 = (const float*)d_in[5];
    const float* b3 = (const float*)d_in[6];
    const float* W4 = (const float*)d_in[7];
    const float* b4 = (const float*)d_in[8];
    float* out = (float*)d_out;

    void *p_h1, *p_h2, *p_joints;
    cudaGetSymbolAddress(&p_h1, g_h1);
    cudaGetSymbolAddress(&p_h2, g_h2);
    cudaGetSymbolAddress(&p_joints, g_joints);
    float* h1 = (float*)p_h1;
    float* h2 = (float*)p_h2;
    float* joints = (float*)p_joints;

    // Layer 1
    layer1_kernel<<<(BATCH * HDIM) / 256, 256>>>(x, W1, b1, h1);

    // Layer 2: h2 = lrelu(h1 @ W2 + b2)
    {
        dim3 grid(HDIM / 128, BATCH / 128);
        gemm_bias_act<0><<<grid, 256>>>(h1, W2, b2, h2, BATCH, HDIM, HDIM);
    }
    // Layer 3: h1 = lrelu(h2 @ W3 + b3)  (reuse h1 buffer)
    {
        dim3 grid(HDIM / 128, BATCH / 128);
        gemm_bias_act<0><<<grid, 256>>>(h2, W3, b3, h1, BATCH, HDIM, HDIM);
    }
    // Layer 4: joints = tanh(h1 @ W4 + b4), N=256
    {
        dim3 grid(256 / 128, BATCH / 128);
        gemm_bias_act<1><<<grid, 256>>>(h1, W4, b4, joints, BATCH, 256, HDIM);
    }

    // FK chain
    fk_kernel<<<BATCH / 256, 256>>>(joints, out);
}

// round 3
// speedup vs baseline: 2.4532x; 2.4532x over previous
#include <cuda_runtime.h>
#include <cuda_bf16.h>
#include <math.h>
#include <stdint.h>

#define BATCH 16384
#define HDIM  1024
#define NJ    64

// ---------------------------------------------------------------------------
// Scratch (__device__ globals; allocation-free contract)
// ---------------------------------------------------------------------------
__device__ __nv_bfloat16 g_a_hi[BATCH * HDIM];
__device__ __nv_bfloat16 g_a_lo[BATCH * HDIM];
__device__ __nv_bfloat16 g_b_hi[BATCH * HDIM];
__device__ __nv_bfloat16 g_b_lo[BATCH * HDIM];
__device__ __nv_bfloat16 g_w2t_hi[HDIM * HDIM];
__device__ __nv_bfloat16 g_w2t_lo[HDIM * HDIM];
__device__ __nv_bfloat16 g_w3t_hi[HDIM * HDIM];
__device__ __nv_bfloat16 g_w3t_lo[HDIM * HDIM];
__device__ __nv_bfloat16 g_w4t_hi[256 * HDIM];
__device__ __nv_bfloat16 g_w4t_lo[256 * HDIM];
__device__ float g_joints[BATCH * 256];

// ---------------------------------------------------------------------------
// Layer 1: h1 = lrelu(x @ W1 + b1), write bf16 split
// ---------------------------------------------------------------------------
__global__ void layer1_split_kernel(const float* __restrict__ x,
                                    const float* __restrict__ W1,
                                    const float* __restrict__ b1,
                                    __nv_bfloat16* __restrict__ ohi,
                                    __nv_bfloat16* __restrict__ olo) {
    int idx = blockIdx.x * blockDim.x + threadIdx.x;
    int b = idx >> 10;
    int n = idx & (HDIM - 1);
    float x0 = x[b * 3 + 0], x1 = x[b * 3 + 1], x2 = x[b * 3 + 2];
    float v = b1[n];
    v = fmaf(x2, W1[2 * HDIM + n], v);
    v = fmaf(x1, W1[1 * HDIM + n], v);
    v = fmaf(x0, W1[0 * HDIM + n], v);
    v = (v >= 0.0f) ? v : 0.01f * v;
    __nv_bfloat16 h = __float2bfloat16(v);
    ohi[idx] = h;
    olo[idx] = __float2bfloat16(v - __bfloat162float(h));
}

// ---------------------------------------------------------------------------
// Transpose + split: W[K,N] fp32 -> Wt_hi/lo [N,K] bf16
// ---------------------------------------------------------------------------
__global__ void transpose_split_kernel(const float* __restrict__ W,
                                       __nv_bfloat16* __restrict__ Th,
                                       __nv_bfloat16* __restrict__ Tl,
                                       int K, int N) {
    __shared__ float s[32][33];
    int n0 = blockIdx.x * 32, k0 = blockIdx.y * 32;
    int tx = threadIdx.x, ty = threadIdx.y;
#pragma unroll
    for (int i = 0; i < 32; i += 8)
        s[ty + i][tx] = W[(size_t)(k0 + ty + i) * N + n0 + tx];
    __syncthreads();
#pragma unroll
    for (int i = 0; i < 32; i += 8) {
        float v = s[tx][ty + i];
        __nv_bfloat16 h = __float2bfloat16(v);
        size_t o = (size_t)(n0 + ty + i) * K + k0 + tx;
        Th[o] = h;
        Tl[o] = __float2bfloat16(v - __bfloat162float(h));
    }
}

// ---------------------------------------------------------------------------
// mma.sync bf16 GEMM, 3-pass split precision.
// C[M,Ntot] = act(A @ Bt^T + bias)
// A(hi/lo): [M,K] bf16 row-major.  Bt(hi/lo): [Ntot,K] bf16 row-major.
// CTA 128x128, 256 thr, warp grid 2(m)x4(n), warp tile 64x32, K-chunk 64.
// smem rows padded 64->72 bf16 (144B stride): LDS frag loads conflict-free.
// ---------------------------------------------------------------------------
#define KC        64
#define SPADE     72                       // padded row, elems
#define SPADU     36                       // padded row, u32
#define TILE_B    (128 * SPADE * 2)        // 18432 bytes per tile
#define STAGE_B   (4 * TILE_B)             // 73728
#define SMEM_TOT  (2 * STAGE_B)            // 147456

__device__ __forceinline__ void mma16816(float* c, const uint32_t* a,
                                         const uint32_t* b) {
    asm volatile(
        "mma.sync.aligned.m16n8k16.row.col.f32.bf16.bf16.f32 "
        "{%0,%1,%2,%3}, {%4,%5,%6,%7}, {%8,%9}, {%0,%1,%2,%3};"
        : "+f"(c[0]), "+f"(c[1]), "+f"(c[2]), "+f"(c[3])
        : "r"(a[0]), "r"(a[1]), "r"(a[2]), "r"(a[3]), "r"(b[0]), "r"(b[1]));
}

__device__ __forceinline__ void cp16(uint32_t dst, const void* src) {
    asm volatile("cp.async.cg.shared.global [%0], [%1], 16;"
                 :: "r"(dst), "l"(src) : "memory");
}

__device__ __forceinline__ uint32_t smem_u32p(const void* p) {
    uint32_t a;
    asm("{ .reg .u64 t; cvta.to.shared.u64 t, %1; cvt.u32.u64 %0, t; }"
        : "=r"(a) : "l"(p));
    return a;
}

// load 128 rows x 64 bf16 from g[(row0+r)*ldk + k0 ...] into padded smem tile
__device__ __forceinline__ void load_tile(uint32_t sdst,
                                          const __nv_bfloat16* __restrict__ g,
                                          int row0, int k0, int ldk, int tid) {
#pragma unroll
    for (int q = 0; q < 4; q++) {
        int e = q * 256 + tid;          // 0..1023
        int r = e >> 3, c = e & 7;      // 8 x 16B per row
        const char* src = (const char*)(g + (size_t)(row0 + r) * ldk + k0) + c * 16;
        cp16(sdst + (uint32_t)(r * 144 + c * 16), src);
    }
}

template <int ACT>
__global__ __launch_bounds__(256)
void gemm_mma(const __nv_bfloat16* __restrict__ Ahi,
              const __nv_bfloat16* __restrict__ Alo,
              const __nv_bfloat16* __restrict__ Bhi,
              const __nv_bfloat16* __restrict__ Blo,
              const float* __restrict__ bias,
              __nv_bfloat16* __restrict__ Ohi,
              __nv_bfloat16* __restrict__ Olo,
              float* __restrict__ Of,
              int Ntot, int K) {
    extern __shared__ char smem[];
    const uint32_t sb = smem_u32p(smem);
    const int tid = threadIdx.x;
    const int wid = tid >> 5;
    const int lid = tid & 31;
    const int gid = lid >> 2;       // 0..7
    const int tig = lid & 3;        // 0..3
    const int wm = wid & 1;         // 0..1  -> m offset wm*64
    const int wn = wid >> 1;        // 0..3  -> n offset wn*32
    const int m0 = blockIdx.y * 128;
    const int n0 = blockIdx.x * 128;

    const uint32_t* s32 = (const uint32_t*)smem;

    float c[4][4][4];
#pragma unroll
    for (int i = 0; i < 4; i++)
#pragma unroll
        for (int j = 0; j < 4; j++)
#pragma unroll
            for (int e = 0; e < 4; e++) c[i][j][e] = 0.0f;

    const int NCH = K >> 6;

    // prologue: stages 0,1
#pragma unroll
    for (int p = 0; p < 2; p++) {
        uint32_t st = sb + (uint32_t)p * STAGE_B;
        load_tile(st + 0 * TILE_B, Ahi, m0, p * KC, K, tid);
        load_tile(st + 1 * TILE_B, Alo, m0, p * KC, K, tid);
        load_tile(st + 2 * TILE_B, Bhi, n0, p * KC, K, tid);
        load_tile(st + 3 * TILE_B, Blo, n0, p * KC, K, tid);
        asm volatile("cp.async.commit_group;" ::: "memory");
    }

    for (int ch = 0; ch < NCH; ch++) {
        if (ch + 1 < NCH)
            asm volatile("cp.async.wait_group 1;" ::: "memory");
        else
            asm volatile("cp.async.wait_group 0;" ::: "memory");
        __syncthreads();

        const int stg = ch & 1;
        // u32 base indices into the 4 tiles of this stage
        const uint32_t u_ah = (uint32_t)(stg * STAGE_B / 4) + 0 * (TILE_B / 4);
        const uint32_t u_al = u_ah + (TILE_B / 4);
        const uint32_t u_bh = u_ah + 2 * (TILE_B / 4);
        const uint32_t u_bl = u_ah + 3 * (TILE_B / 4);

#pragma unroll
        for (int kk = 0; kk < 4; kk++) {
            const int ku = kk * 8 + tig;   // u32 col base (k/2 + t)
            uint32_t ah[4][4], al[4][4], bh[4][2], bl[4][2];
#pragma unroll
            for (int mt = 0; mt < 4; mt++) {
                int r = wm * 64 + mt * 16 + gid;
                ah[mt][0] = s32[u_ah + r * SPADU + ku];
                ah[mt][1] = s32[u_ah + (r + 8) * SPADU + ku];
                ah[mt][2] = s32[u_ah + r * SPADU + ku + 4];
                ah[mt][3] = s32[u_ah + (r + 8) * SPADU + ku + 4];
                al[mt][0] = s32[u_al + r * SPADU + ku];
                al[mt][1] = s32[u_al + (r + 8) * SPADU + ku];
                al[mt][2] = s32[u_al + r * SPADU + ku + 4];
                al[mt][3] = s32[u_al + (r + 8) * SPADU + ku + 4];
            }
#pragma unroll
            for (int nt = 0; nt < 4; nt++) {
                int nr = wn * 32 + nt * 8 + gid;
                bh[nt][0] = s32[u_bh + nr * SPADU + ku];
                bh[nt][1] = s32[u_bh + nr * SPADU + ku + 4];
                bl[nt][0] = s32[u_bl + nr * SPADU + ku];
                bl[nt][1] = s32[u_bl + nr * SPADU + ku + 4];
            }
#pragma unroll
            for (int mt = 0; mt < 4; mt++)
#pragma unroll
                for (int nt = 0; nt < 4; nt++) {
                    mma16816(c[mt][nt], ah[mt], bh[nt]);
                    mma16816(c[mt][nt], ah[mt], bl[nt]);
                    mma16816(c[mt][nt], al[mt], bh[nt]);
                }
        }

        __syncthreads();
        if (ch + 2 < NCH) {
            uint32_t st = sb + (uint32_t)stg * STAGE_B;
            int k0 = (ch + 2) * KC;
            load_tile(st + 0 * TILE_B, Ahi, m0, k0, K, tid);
            load_tile(st + 1 * TILE_B, Alo, m0, k0, K, tid);
            load_tile(st + 2 * TILE_B, Bhi, n0, k0, K, tid);
            load_tile(st + 3 * TILE_B, Blo, n0, k0, K, tid);
            asm volatile("cp.async.commit_group;" ::: "memory");
        }
    }

    // Epilogue straight from registers
#pragma unroll
    for (int mt = 0; mt < 4; mt++) {
        int r0 = m0 + wm * 64 + mt * 16 + gid;
#pragma unroll
        for (int nt = 0; nt < 4; nt++) {
            int col = n0 + wn * 32 + nt * 8 + tig * 2;
            float bv0 = bias[col], bv1 = bias[col + 1];
            float v00 = c[mt][nt][0] + bv0;
            float v01 = c[mt][nt][1] + bv1;
            float v10 = c[mt][nt][2] + bv0;
            float v11 = c[mt][nt][3] + bv1;
            if (ACT == 0) {
                v00 = (v00 >= 0.f) ? v00 : 0.01f * v00;
                v01 = (v01 >= 0.f) ? v01 : 0.01f * v01;
                v10 = (v10 >= 0.f) ? v10 : 0.01f * v10;
                v11 = (v11 >= 0.f) ? v11 : 0.01f * v11;
                __nv_bfloat162 hh0, hh1, ll0, ll1;
                hh0.x = __float2bfloat16(v00);
                hh0.y = __float2bfloat16(v01);
                hh1.x = __float2bfloat16(v10);
                hh1.y = __float2bfloat16(v11);
                ll0.x = __float2bfloat16(v00 - __bfloat162float(hh0.x));
                ll0.y = __float2bfloat16(v01 - __bfloat162float(hh0.y));
                ll1.x = __float2bfloat16(v10 - __bfloat162float(hh1.x));
                ll1.y = __float2bfloat16(v11 - __bfloat162float(hh1.y));
                size_t o0 = (size_t)r0 * Ntot + col;
                size_t o1 = (size_t)(r0 + 8) * Ntot + col;
                *(__nv_bfloat162*)(Ohi + o0) = hh0;
                *(__nv_bfloat162*)(Ohi + o1) = hh1;
                *(__nv_bfloat162*)(Olo + o0) = ll0;
                *(__nv_bfloat162*)(Olo + o1) = ll1;
            } else {
                size_t o0 = (size_t)r0 * Ntot + col;
                size_t o1 = (size_t)(r0 + 8) * Ntot + col;
                float2 f0 = make_float2(tanhf(v00), tanhf(v01));
                float2 f1 = make_float2(tanhf(v10), tanhf(v11));
                *(float2*)(Of + o0) = f0;
                *(float2*)(Of + o1) = f1;
            }
        }
    }
}

// ---------------------------------------------------------------------------
// FK chain
// ---------------------------------------------------------------------------
__global__ void fk_kernel(const float* __restrict__ joints,
                          float* __restrict__ out) {
    int b = blockIdx.x * blockDim.x + threadIdx.x;
    if (b >= BATCH) return;

    const float4* q4 = reinterpret_cast<const float4*>(joints + (size_t)b * 256);
    float* o = out + (size_t)b * NJ * 3;

    float r00 = 1.f, r01 = 0.f, r02 = 0.f;
    float r10 = 0.f, r11 = 1.f, r12 = 0.f;
    float r20 = 0.f, r21 = 0.f, r22 = 1.f;
    float t0 = 0.f, t1 = 0.f, t2 = 0.f;

    for (int j = 0; j < NJ; j++) {
        float4 q = q4[j];
        float w = q.x, x = q.y, y = q.z, z = q.w;
        float s = 2.0f / (w * w + x * x + y * y + z * z);

        float R00 = 1.0f - s * (y * y + z * z);
        float R01 = s * (x * y - z * w);
        float R02 = s * (x * z + y * w);
        float R10 = s * (x * y + z * w);
        float R11 = 1.0f - s * (x * x + z * z);
        float R12 = s * (y * z - x * w);
        float R20 = s * (x * z - y * w);
        float R21 = s * (y * z + x * w);
        float R22 = 1.0f - s * (x * x + y * y);

        float n00 = r00 * R00 + r01 * R10 + r02 * R20;
        float n01 = r00 * R01 + r01 * R11 + r02 * R21;
        float n02 = r00 * R02 + r01 * R12 + r02 * R22;
        float n10 = r10 * R00 + r11 * R10 + r12 * R20;
        float n11 = r10 * R01 + r11 * R11 + r12 * R21;
        float n12 = r10 * R02 + r11 * R12 + r12 * R22;
        float n20 = r20 * R00 + r21 * R10 + r22 * R20;
        float n21 = r20 * R01 + r21 * R11 + r22 * R21;
        float n22 = r20 * R02 + r21 * R12 + r22 * R22;

        t0 += n01; t1 += n11; t2 += n21;

        r00 = n00; r01 = n01; r02 = n02;
        r10 = n10; r11 = n11; r12 = n12;
        r20 = n20; r21 = n21; r22 = n22;

        o[j * 3 + 0] = t0;
        o[j * 3 + 1] = t1;
        o[j * 3 + 2] = t2;
    }
}

// ---------------------------------------------------------------------------
// Launch
// ---------------------------------------------------------------------------
extern "C" void kernel_launch(void* const* d_in, const int* in_sizes, int n_in,
                              void* d_out, int out_size) {
    const float* x  = (const float*)d_in[0];
    const float* W1 = (const float*)d_in[1];
    const float* b1 = (const float*)d_in[2];
    const float* W2 = (const float*)d_in[3];
    const float* b2 = (const float*)d_in[4];
    const float* W3 = (const float*)d_in[5];
    const float* b3 = (const float*)d_in[6];
    const float* W4 = (const float*)d_in[7];
    const float* b4 = (const float*)d_in[8];
    float* out = (float*)d_out;

    void* p;
#define SYM(v, s) cudaGetSymbolAddress(&p, s); auto* v = (__nv_bfloat16*)p;
    SYM(a_hi, g_a_hi); SYM(a_lo, g_a_lo);
    SYM(b_hi, g_b_hi); SYM(b_lo, g_b_lo);
    SYM(w2h, g_w2t_hi); SYM(w2l, g_w2t_lo);
    SYM(w3h, g_w3t_hi); SYM(w3l, g_w3t_lo);
    SYM(w4h, g_w4t_hi); SYM(w4l, g_w4t_lo);
#undef SYM
    cudaGetSymbolAddress(&p, g_joints);
    float* joints = (float*)p;

    cudaFuncSetAttribute(gemm_mma<0>,
                         cudaFuncAttributeMaxDynamicSharedMemorySize, SMEM_TOT);
    cudaFuncSetAttribute(gemm_mma<1>,
                         cudaFuncAttributeMaxDynamicSharedMemorySize, SMEM_TOT);

    // Weight transposes + splits
    {
        dim3 blk(32, 8);
        transpose_split_kernel<<<dim3(HDIM / 32, HDIM / 32), blk>>>(W2, w2h, w2l, HDIM, HDIM);
        transpose_split_kernel<<<dim3(HDIM / 32, HDIM / 32), blk>>>(W3, w3h, w3l, HDIM, HDIM);
        transpose_split_kernel<<<dim3(256 / 32,  HDIM / 32), blk>>>(W4, w4h, w4l, HDIM, 256);
    }

    // Layer 1
    layer1_split_kernel<<<(BATCH * HDIM) / 256, 256>>>(x, W1, b1, a_hi, a_lo);

    // Layer 2
    gemm_mma<0><<<dim3(HDIM / 128, BATCH / 128), 256, SMEM_TOT>>>(
        a_hi, a_lo, w2h, w2l, b2, b_hi, b_lo, nullptr, HDIM, HDIM);
    // Layer 3
    gemm_mma<0><<<dim3(HDIM / 128, BATCH / 128), 256, SMEM_TOT>>>(
        b_hi, b_lo, w3h, w3l, b3, a_hi, a_lo, nullptr, HDIM, HDIM);
    // Layer 4
    gemm_mma<1><<<dim3(256 / 128, BATCH / 128), 256, SMEM_TOT>>>(
        a_hi, a_lo, w4h, w4l, b4, nullptr, nullptr, joints, 256, HDIM);

    // FK chain
    fk_kernel<<<BATCH / 256, 256>>>(joints, out);
}